// round 2
// baseline (speedup 1.0000x reference)
#include <cuda_runtime.h>

#define NN 50000
#define EE 600000
#define DH 128

// -------- device scratch (no allocations allowed) --------
__device__ float g_xw[NN * DH];      // dinv-scaled x@W
__device__ float g_h[NN * DH];       // layer output
__device__ float g_dinv[NN];
__device__ int   g_count[NN];
__device__ int   g_off[NN + 1];
__device__ int   g_cursor[NN];
__device__ int   g_csr[EE];          // source (row) node per edge, bucketed by col
__device__ float g_p[NN * 8];        // per-node projections: [0:4]=h@Wfc_top, [4:8]=h@Wfc_bot

// -------- CSR construction --------
__global__ void k_zero(int n) {
    int i = blockIdx.x * blockDim.x + threadIdx.x;
    if (i < n) g_count[i] = 0;
}

__global__ void k_hist(const int* __restrict__ ei, int E) {
    int e = blockIdx.x * blockDim.x + threadIdx.x;
    if (e < E) {
        int c = ei[E + e];
        atomicAdd(&g_count[c], 1);
    }
}

// single-block exclusive scan of counts; also computes dinv = rsqrt(count+1)
__global__ void k_scan(int n) {
    __shared__ int part[1024];
    int tid = threadIdx.x;
    int chunk = (n + 1023) >> 10;
    int s = tid * chunk;
    int e = min(s + chunk, n);
    int sum = 0;
    for (int i = s; i < e; i++) sum += g_count[i];
    part[tid] = sum;
    __syncthreads();
    for (int off = 1; off < 1024; off <<= 1) {
        int v = (tid >= off) ? part[tid - off] : 0;
        __syncthreads();
        part[tid] += v;
        __syncthreads();
    }
    int run = tid ? part[tid - 1] : 0;
    for (int i = s; i < e; i++) {
        int c = g_count[i];
        g_off[i] = run;
        g_cursor[i] = run;
        g_dinv[i] = rsqrtf((float)(c + 1));
        run += c;
    }
    if (tid == 1023) g_off[n] = part[1023];
}

__global__ void k_scatter(const int* __restrict__ ei, int E) {
    int e = blockIdx.x * blockDim.x + threadIdx.x;
    if (e < E) {
        int c = ei[E + e];
        int p = atomicAdd(&g_cursor[c], 1);
        g_csr[p] = ei[e];
    }
}

// -------- GEMM: C[n x 128] = A[n x 128] * B[128 x 128], epilogue C *= dinv[row] --------
// BM=64, BN=128, BK=32; 256 threads; each thread -> 8 rows x 4 cols
__global__ void k_gemm(const float* __restrict__ A, const float* __restrict__ B,
                       float* __restrict__ C, int n) {
    __shared__ __align__(16) float As[64][32];
    __shared__ __align__(16) float Bs[32][128];
    int t = threadIdx.x;
    int row0 = blockIdx.x * 64;
    int tx = t & 31;   // 32 col-groups of 4
    int ty = t >> 5;   // 8 row-groups of 8
    float4 acc[8];
#pragma unroll
    for (int i = 0; i < 8; i++) acc[i] = make_float4(0.f, 0.f, 0.f, 0.f);

    for (int kt = 0; kt < 4; kt++) {
        // load A tile: 64x32 = 512 float4, 2 per thread
#pragma unroll
        for (int j = 0; j < 2; j++) {
            int f = t + 256 * j;
            int r = f >> 3;
            int kk = (f & 7) << 2;
            int gr = row0 + r;
            float4 v = (gr < n) ? *(const float4*)&A[gr * 128 + kt * 32 + kk]
                                : make_float4(0.f, 0.f, 0.f, 0.f);
            *(float4*)&As[r][kk] = v;
        }
        // load B tile: 32x128 = 1024 float4, 4 per thread
#pragma unroll
        for (int j = 0; j < 4; j++) {
            int f = t + 256 * j;
            int r = f >> 5;
            int c4 = (f & 31) << 2;
            *(float4*)&Bs[r][c4] = *(const float4*)&B[(kt * 32 + r) * 128 + c4];
        }
        __syncthreads();
#pragma unroll
        for (int k = 0; k < 32; k++) {
            float4 b4 = *(float4*)&Bs[k][tx * 4];
#pragma unroll
            for (int i = 0; i < 8; i++) {
                float a = As[ty * 8 + i][k];
                acc[i].x = fmaf(a, b4.x, acc[i].x);
                acc[i].y = fmaf(a, b4.y, acc[i].y);
                acc[i].z = fmaf(a, b4.z, acc[i].z);
                acc[i].w = fmaf(a, b4.w, acc[i].w);
            }
        }
        __syncthreads();
    }
#pragma unroll
    for (int i = 0; i < 8; i++) {
        int gr = row0 + ty * 8 + i;
        if (gr < n) {
            float s = g_dinv[gr];
            float4 o = make_float4(acc[i].x * s, acc[i].y * s, acc[i].z * s, acc[i].w * s);
            *(float4*)&C[gr * 128 + tx * 4] = o;
        }
    }
}

// -------- aggregation: out[c] = relu(dinv[c] * (xws[c] + sum_{e: col==c} xws[row_e]) + b) --------
__global__ void k_agg(const float* __restrict__ xw, const float* __restrict__ bias,
                      float* __restrict__ out) {
    int c = blockIdx.x;
    int t = threadIdx.x;
    float acc = xw[c * DH + t];  // self loop term (already dinv[c]-scaled)
    int s = g_off[c], e = g_off[c + 1];
    for (int k = s; k < e; k++) {
        int r = g_csr[k];
        acc += xw[r * DH + t];
    }
    out[c * DH + t] = fmaxf(fmaf(g_dinv[c], acc, bias[t]), 0.f);
}

// -------- per-node projection: p[i][j] = h[i] @ Wfc[0:128,j]; p[i][4+j] = h[i] @ Wfc[128:256,j] --------
__global__ void k_proj(const float* __restrict__ h, const float* __restrict__ Wfc, int n) {
    __shared__ float W[256 * 4];
    int t = threadIdx.x;
    for (int i = t; i < 1024; i += 256) W[i] = Wfc[i];
    __syncthreads();
    int warp = t >> 5, lane = t & 31;
    int node = blockIdx.x * 8 + warp;
    if (node >= n) return;
    float hv[4];
#pragma unroll
    for (int q = 0; q < 4; q++) hv[q] = h[node * 128 + lane + 32 * q];
    float p[8];
#pragma unroll
    for (int j = 0; j < 4; j++) {
        float a = 0.f, b = 0.f;
#pragma unroll
        for (int q = 0; q < 4; q++) {
            int k = lane + 32 * q;
            a = fmaf(hv[q], W[k * 4 + j], a);
            b = fmaf(hv[q], W[(128 + k) * 4 + j], b);
        }
        p[j] = a;
        p[4 + j] = b;
    }
#pragma unroll
    for (int j = 0; j < 8; j++) {
        float v = p[j];
#pragma unroll
        for (int o = 16; o > 0; o >>= 1) v += __shfl_xor_sync(0xffffffffu, v, o);
        if (lane == 0) g_p[node * 8 + j] = v;
    }
}

// -------- edge scoring + log-softmax --------
__global__ void k_edge(const int* __restrict__ ei, const float* __restrict__ bfc,
                       float* __restrict__ out, int E) {
    int e = blockIdx.x * blockDim.x + threadIdx.x;
    if (e >= E) return;
    int r = ei[e];
    int c = ei[E + e];
    float4 pa = *(const float4*)&g_p[r * 8];
    float4 pb = *(const float4*)&g_p[c * 8 + 4];
    float s0 = pa.x + pb.x + bfc[0];
    float s1 = pa.y + pb.y + bfc[1];
    float s2 = pa.z + pb.z + bfc[2];
    float s3 = pa.w + pb.w + bfc[3];
    float m = fmaxf(fmaxf(s0, s1), fmaxf(s2, s3));
    float t0 = expf(s0 - m), t1 = expf(s1 - m), t2 = expf(s2 - m), t3 = expf(s3 - m);
    float l = m + logf(t0 + t1 + t2 + t3);
    *(float4*)&out[e * 4] = make_float4(s0 - l, s1 - l, s2 - l, s3 - l);
}

extern "C" void kernel_launch(void* const* d_in, const int* in_sizes, int n_in,
                              void* d_out, int out_size) {
    const float* x   = (const float*)d_in[0];
    const int*   ei  = (const int*)d_in[1];
    const float* W1  = (const float*)d_in[2];
    const float* b1  = (const float*)d_in[3];
    const float* W2  = (const float*)d_in[4];
    const float* b2  = (const float*)d_in[5];
    const float* Wfc = (const float*)d_in[6];
    const float* bfc = (const float*)d_in[7];
    float* out = (float*)d_out;

    int n = in_sizes[0] / DH;
    int E = in_sizes[1] / 2;

    float *xw, *h;
    cudaGetSymbolAddress((void**)&xw, g_xw);
    cudaGetSymbolAddress((void**)&h, g_h);

    int tb = 256;
    // CSR build
    k_zero<<<(n + tb - 1) / tb, tb>>>(n);
    k_hist<<<(E + tb - 1) / tb, tb>>>(ei, E);
    k_scan<<<1, 1024>>>(n);
    k_scatter<<<(E + tb - 1) / tb, tb>>>(ei, E);

    // layer 1
    k_gemm<<<(n + 63) / 64, 256>>>(x, W1, xw, n);
    k_agg<<<n, DH>>>(xw, b1, h);
    // layer 2
    k_gemm<<<(n + 63) / 64, 256>>>(h, W2, xw, n);
    k_agg<<<n, DH>>>(xw, b2, h);

    // edge classifier
    k_proj<<<(n + 7) / 8, 256>>>(h, Wfc, n);
    k_edge<<<(E + tb - 1) / tb, tb>>>(ei, bfc, out, E);
}

// round 3
// speedup vs baseline: 1.1684x; 1.1684x over previous
#include <cuda_runtime.h>

#define NN 50000
#define EE 600000
#define DH 128

typedef unsigned long long ull;

// -------- device scratch (no allocations allowed) --------
__device__ float g_xw[NN * DH];      // dinv-scaled x@W
__device__ float g_h[NN * DH];       // layer output
__device__ float g_dinv[NN];
__device__ int   g_count[NN];
__device__ int   g_off[NN + 1];
__device__ int   g_cursor[NN];
__device__ int   g_csr[EE];          // source (row) node per edge, bucketed by col
__device__ float g_p[NN * 8];        // per-node projections

// -------- packed f32x2 helpers --------
__device__ __forceinline__ ull pack_dup(float x) {
    ull r; asm("mov.b64 %0, {%1, %1};" : "=l"(r) : "f"(x)); return r;
}
__device__ __forceinline__ ull pack2(float x, float y) {
    ull r; asm("mov.b64 %0, {%1, %2};" : "=l"(r) : "f"(x), "f"(y)); return r;
}
__device__ __forceinline__ void fma2(ull& d, ull a, ull b) {
    asm("fma.rn.f32x2 %0, %1, %2, %0;" : "+l"(d) : "l"(a), "l"(b));
}
__device__ __forceinline__ float2 unpack2(ull v) {
    float2 f; asm("mov.b64 {%0, %1}, %2;" : "=f"(f.x), "=f"(f.y) : "l"(v)); return f;
}

// -------- CSR construction --------
__global__ void k_zero(int n) {
    int i = blockIdx.x * blockDim.x + threadIdx.x;
    if (i < n) g_count[i] = 0;
}

__global__ void k_hist(const int* __restrict__ ei, int E) {
    int e = blockIdx.x * blockDim.x + threadIdx.x;
    if (e < E) atomicAdd(&g_count[ei[E + e]], 1);
}

// single-block exclusive scan of counts; also computes dinv = rsqrt(count+1)
__global__ void k_scan(int n) {
    __shared__ int part[1024];
    int tid = threadIdx.x;
    int chunk = (n + 1023) >> 10;
    int s = tid * chunk;
    int e = min(s + chunk, n);
    int sum = 0;
    for (int i = s; i < e; i++) sum += g_count[i];
    part[tid] = sum;
    __syncthreads();
    for (int off = 1; off < 1024; off <<= 1) {
        int v = (tid >= off) ? part[tid - off] : 0;
        __syncthreads();
        part[tid] += v;
        __syncthreads();
    }
    int run = tid ? part[tid - 1] : 0;
    for (int i = s; i < e; i++) {
        int c = g_count[i];
        g_off[i] = run;
        g_cursor[i] = run;
        g_dinv[i] = rsqrtf((float)(c + 1));
        run += c;
    }
    if (tid == 1023) g_off[n] = part[1023];
}

__global__ void k_scatter(const int* __restrict__ ei, int E) {
    int e = blockIdx.x * blockDim.x + threadIdx.x;
    if (e < E) {
        int c = ei[E + e];
        int p = atomicAdd(&g_cursor[c], 1);
        g_csr[p] = ei[e];
    }
}

// -------- GEMM: C[n x 128] = A[n x 128] * B[128 x 128], epilogue *= dinv[row] --------
// BM=64, BN=128, BK=32, 256 threads; FFMA2 packed across row pairs.
__global__ void k_gemm(const float* __restrict__ A, const float* __restrict__ B,
                       float* __restrict__ C, int n) {
    __shared__ __align__(16) float As[32][66];   // k-major: As[k][row]
    __shared__ __align__(16) float Bs[32][128];
    int t = threadIdx.x;
    int row0 = blockIdx.x * 64;
    int tx = t & 31;   // col-group (4 cols)
    int ty = t >> 5;   // row-group (8 rows = 4 pairs)
    ull acc[4][4];
#pragma unroll
    for (int i = 0; i < 4; i++)
#pragma unroll
        for (int c = 0; c < 4; c++) acc[i][c] = 0ull;   // bits of (+0.f, +0.f)

    for (int kt = 0; kt < 4; kt++) {
        // A tile (transposed store): 512 float4 reads, 2 per thread
#pragma unroll
        for (int j = 0; j < 2; j++) {
            int f = t + 256 * j;
            int r = f >> 3;
            int k0 = (f & 7) << 2;
            int gr = row0 + r;
            float4 v = (gr < n) ? *(const float4*)&A[gr * 128 + kt * 32 + k0]
                                : make_float4(0.f, 0.f, 0.f, 0.f);
            As[k0 + 0][r] = v.x;
            As[k0 + 1][r] = v.y;
            As[k0 + 2][r] = v.z;
            As[k0 + 3][r] = v.w;
        }
        // B tile: 1024 float4, 4 per thread
#pragma unroll
        for (int j = 0; j < 4; j++) {
            int f = t + 256 * j;
            int r = f >> 5;
            int c4 = (f & 31) << 2;
            *(float4*)&Bs[r][c4] = *(const float4*)&B[(kt * 32 + r) * 128 + c4];
        }
        __syncthreads();
#pragma unroll
        for (int k = 0; k < 32; k++) {
            float4 b4 = *(float4*)&Bs[k][tx * 4];
            ull bd0 = pack_dup(b4.x);
            ull bd1 = pack_dup(b4.y);
            ull bd2 = pack_dup(b4.z);
            ull bd3 = pack_dup(b4.w);
#pragma unroll
            for (int i = 0; i < 4; i++) {
                float2 a2 = *(float2*)&As[k][ty * 8 + 2 * i];
                ull av = pack2(a2.x, a2.y);
                fma2(acc[i][0], av, bd0);
                fma2(acc[i][1], av, bd1);
                fma2(acc[i][2], av, bd2);
                fma2(acc[i][3], av, bd3);
            }
        }
        __syncthreads();
    }
#pragma unroll
    for (int i = 0; i < 4; i++) {
        float2 c0 = unpack2(acc[i][0]);
        float2 c1 = unpack2(acc[i][1]);
        float2 c2 = unpack2(acc[i][2]);
        float2 c3 = unpack2(acc[i][3]);
        int r0 = row0 + ty * 8 + 2 * i;
        int r1 = r0 + 1;
        if (r0 < n) {
            float s = g_dinv[r0];
            *(float4*)&C[r0 * 128 + tx * 4] =
                make_float4(c0.x * s, c1.x * s, c2.x * s, c3.x * s);
        }
        if (r1 < n) {
            float s = g_dinv[r1];
            *(float4*)&C[r1 * 128 + tx * 4] =
                make_float4(c0.y * s, c1.y * s, c2.y * s, c3.y * s);
        }
    }
}

// -------- aggregation: one warp per node, float4 per lane, 4-way unrolled --------
__global__ void k_agg(const float4* __restrict__ xw4, const float4* __restrict__ bias4,
                      float4* __restrict__ out4, int n) {
    int warp = threadIdx.x >> 5, lane = threadIdx.x & 31;
    int c = blockIdx.x * 4 + warp;
    if (c >= n) return;
    float4 acc = xw4[c * 32 + lane];   // self-loop term (already dinv[c]-scaled)
    int s = g_off[c], e = g_off[c + 1];
    int k = s;
    for (; k + 4 <= e; k += 4) {
        int r0 = g_csr[k], r1 = g_csr[k + 1], r2 = g_csr[k + 2], r3 = g_csr[k + 3];
        float4 v0 = xw4[r0 * 32 + lane];
        float4 v1 = xw4[r1 * 32 + lane];
        float4 v2 = xw4[r2 * 32 + lane];
        float4 v3 = xw4[r3 * 32 + lane];
        acc.x += (v0.x + v1.x) + (v2.x + v3.x);
        acc.y += (v0.y + v1.y) + (v2.y + v3.y);
        acc.z += (v0.z + v1.z) + (v2.z + v3.z);
        acc.w += (v0.w + v1.w) + (v2.w + v3.w);
    }
    for (; k < e; k++) {
        int r = g_csr[k];
        float4 v = xw4[r * 32 + lane];
        acc.x += v.x; acc.y += v.y; acc.z += v.z; acc.w += v.w;
    }
    float di = g_dinv[c];
    float4 b = bias4[lane];
    float4 o;
    o.x = fmaxf(fmaf(di, acc.x, b.x), 0.f);
    o.y = fmaxf(fmaf(di, acc.y, b.y), 0.f);
    o.z = fmaxf(fmaf(di, acc.z, b.z), 0.f);
    o.w = fmaxf(fmaf(di, acc.w, b.w), 0.f);
    out4[c * 32 + lane] = o;
}

// -------- per-node projection --------
__global__ void k_proj(const float* __restrict__ h, const float* __restrict__ Wfc, int n) {
    __shared__ float W[256 * 4];
    int t = threadIdx.x;
    for (int i = t; i < 1024; i += 256) W[i] = Wfc[i];
    __syncthreads();
    int warp = t >> 5, lane = t & 31;
    int node = blockIdx.x * 8 + warp;
    if (node >= n) return;
    float hv[4];
#pragma unroll
    for (int q = 0; q < 4; q++) hv[q] = h[node * 128 + lane + 32 * q];
    float p[8];
#pragma unroll
    for (int j = 0; j < 4; j++) {
        float a = 0.f, b = 0.f;
#pragma unroll
        for (int q = 0; q < 4; q++) {
            int k = lane + 32 * q;
            a = fmaf(hv[q], W[k * 4 + j], a);
            b = fmaf(hv[q], W[(128 + k) * 4 + j], b);
        }
        p[j] = a;
        p[4 + j] = b;
    }
#pragma unroll
    for (int j = 0; j < 8; j++) {
        float v = p[j];
#pragma unroll
        for (int o = 16; o > 0; o >>= 1) v += __shfl_xor_sync(0xffffffffu, v, o);
        if (lane == 0) g_p[node * 8 + j] = v;
    }
}

// -------- edge scoring + log-softmax --------
__global__ void k_edge(const int* __restrict__ ei, const float* __restrict__ bfc,
                       float* __restrict__ out, int E) {
    int e = blockIdx.x * blockDim.x + threadIdx.x;
    if (e >= E) return;
    int r = ei[e];
    int c = ei[E + e];
    float4 pa = *(const float4*)&g_p[r * 8];
    float4 pb = *(const float4*)&g_p[c * 8 + 4];
    float s0 = pa.x + pb.x + bfc[0];
    float s1 = pa.y + pb.y + bfc[1];
    float s2 = pa.z + pb.z + bfc[2];
    float s3 = pa.w + pb.w + bfc[3];
    float m = fmaxf(fmaxf(s0, s1), fmaxf(s2, s3));
    float t0 = expf(s0 - m), t1 = expf(s1 - m), t2 = expf(s2 - m), t3 = expf(s3 - m);
    float l = m + logf(t0 + t1 + t2 + t3);
    *(float4*)&out[e * 4] = make_float4(s0 - l, s1 - l, s2 - l, s3 - l);
}

extern "C" void kernel_launch(void* const* d_in, const int* in_sizes, int n_in,
                              void* d_out, int out_size) {
    const float* x   = (const float*)d_in[0];
    const int*   ei  = (const int*)d_in[1];
    const float* W1  = (const float*)d_in[2];
    const float* b1  = (const float*)d_in[3];
    const float* W2  = (const float*)d_in[4];
    const float* b2  = (const float*)d_in[5];
    const float* Wfc = (const float*)d_in[6];
    const float* bfc = (const float*)d_in[7];
    float* out = (float*)d_out;

    int n = in_sizes[0] / DH;
    int E = in_sizes[1] / 2;

    float *xw, *h;
    cudaGetSymbolAddress((void**)&xw, g_xw);
    cudaGetSymbolAddress((void**)&h, g_h);

    int tb = 256;
    // CSR build
    k_zero<<<(n + tb - 1) / tb, tb>>>(n);
    k_hist<<<(E + tb - 1) / tb, tb>>>(ei, E);
    k_scan<<<1, 1024>>>(n);
    k_scatter<<<(E + tb - 1) / tb, tb>>>(ei, E);

    // layer 1
    k_gemm<<<(n + 63) / 64, 256>>>(x, W1, xw, n);
    k_agg<<<(n + 3) / 4, 128>>>((const float4*)xw, (const float4*)b1, (float4*)h, n);
    // layer 2
    k_gemm<<<(n + 63) / 64, 256>>>(h, W2, xw, n);
    k_agg<<<(n + 3) / 4, 128>>>((const float4*)xw, (const float4*)b2, (float4*)h, n);

    // edge classifier
    k_proj<<<(n + 7) / 8, 256>>>(h, Wfc, n);
    k_edge<<<(E + tb - 1) / tb, tb>>>(ei, bfc, out, E);
}

// round 5
// speedup vs baseline: 1.2884x; 1.1027x over previous
#include <cuda_runtime.h>
#include <cuda_bf16.h>
#include <cstdint>

#define NN 50000
#define NN_PAD 50048          // 391 * 128
#define EE 600000
#define DH 128

// -------- device scratch (no allocations allowed) --------
__device__ float g_xw[NN * DH];                 // dinv-scaled A@W
__device__ float g_h[NN * DH];                  // layer-2 output (fp32, for proj)
__device__ float g_dinv[NN];
__device__ int   g_count[NN];
__device__ int   g_off[NN + 1];
__device__ int   g_cursor[NN];
__device__ int   g_csr[EE];
__device__ float g_p[NN * 8];
__device__ __nv_bfloat16 g_ahi[NN_PAD * DH];    // bf16 split of current GEMM input
__device__ __nv_bfloat16 g_alo[NN_PAD * DH];
__device__ __nv_bfloat16 g_bhi[DH * DH];        // bf16 split of W^T (B[n][k] = W[k][n])
__device__ __nv_bfloat16 g_blo[DH * DH];

__device__ __forceinline__ uint32_t smem_u32(const void* p) {
    uint32_t a;
    asm("{ .reg .u64 t; cvta.to.shared.u64 t, %1; cvt.u32.u64 %0, t; }" : "=r"(a) : "l"(p));
    return a;
}

// -------- CSR construction --------
__global__ void k_zero(int n) {
    int i = blockIdx.x * blockDim.x + threadIdx.x;
    if (i < n) g_count[i] = 0;
}
__global__ void k_hist(const int* __restrict__ ei, int E) {
    int e = blockIdx.x * blockDim.x + threadIdx.x;
    if (e < E) atomicAdd(&g_count[ei[E + e]], 1);
}
__global__ void k_scan(int n) {
    __shared__ int part[1024];
    int tid = threadIdx.x;
    int chunk = (n + 1023) >> 10;
    int s = tid * chunk;
    int e = min(s + chunk, n);
    int sum = 0;
    for (int i = s; i < e; i++) sum += g_count[i];
    part[tid] = sum;
    __syncthreads();
    for (int off = 1; off < 1024; off <<= 1) {
        int v = (tid >= off) ? part[tid - off] : 0;
        __syncthreads();
        part[tid] += v;
        __syncthreads();
    }
    int run = tid ? part[tid - 1] : 0;
    for (int i = s; i < e; i++) {
        int c = g_count[i];
        g_off[i] = run;
        g_cursor[i] = run;
        g_dinv[i] = rsqrtf((float)(c + 1));
        run += c;
    }
    if (tid == 1023) g_off[n] = part[1023];
}
__global__ void k_scatter(const int* __restrict__ ei, int E) {
    int e = blockIdx.x * blockDim.x + threadIdx.x;
    if (e < E) {
        int c = ei[E + e];
        int p = atomicAdd(&g_cursor[c], 1);
        g_csr[p] = ei[e];
    }
}

// -------- bf16 split conversions --------
__global__ void k_convX(const float4* __restrict__ x4, int n) {
    int i = blockIdx.x * blockDim.x + threadIdx.x;   // float4 index
    if (i >= NN_PAD * 32) return;
    int row = i >> 5;
    float4 v = (row < n) ? x4[i] : make_float4(0.f, 0.f, 0.f, 0.f);
    __nv_bfloat162 h01 = __floats2bfloat162_rn(v.x, v.y);
    __nv_bfloat162 h23 = __floats2bfloat162_rn(v.z, v.w);
    float2 f01 = __bfloat1622float2(h01);
    float2 f23 = __bfloat1622float2(h23);
    __nv_bfloat162 l01 = __floats2bfloat162_rn(v.x - f01.x, v.y - f01.y);
    __nv_bfloat162 l23 = __floats2bfloat162_rn(v.z - f23.x, v.w - f23.y);
    __nv_bfloat162* ah = (__nv_bfloat162*)g_ahi;
    __nv_bfloat162* al = (__nv_bfloat162*)g_alo;
    ah[i * 2] = h01; ah[i * 2 + 1] = h23;
    al[i * 2] = l01; al[i * 2 + 1] = l23;
}
__global__ void k_convW(const float* __restrict__ W) {
    int i = blockIdx.x * blockDim.x + threadIdx.x;   // 16384
    int nIdx = i >> 7, k = i & 127;
    float v = W[k * DH + nIdx];                       // transpose: B[n][k] = W[k][n]
    __nv_bfloat16 h = __float2bfloat16(v);
    g_bhi[i] = h;
    g_blo[i] = __float2bfloat16(v - __bfloat162float(h));
}

// ======================= mma.sync (HMMA) GEMM =======================
// C[row,:] = dinv[row] * (A[row,:] @ W) via 3-pass bf16 split.
// CTA: 128 rows x 128 cols, K=128 all resident in smem. 8 warps: 4 m-groups x 2 n-groups.
// Tile layout in smem: row-major 128 rows x 256B, 16B chunks XOR-swizzled:
//   phys_chunk = (c & 8) | ((c ^ row) & 7)
#define SM_AHI  0
#define SM_ALO  32768
#define SM_BHI  65536
#define SM_BLO  98304
#define SM_TOTAL 131072

__device__ __forceinline__ void ldm_x4(uint32_t* r, uint32_t addr) {
    asm volatile("ldmatrix.sync.aligned.m8n8.x4.shared.b16 {%0,%1,%2,%3}, [%4];"
                 : "=r"(r[0]), "=r"(r[1]), "=r"(r[2]), "=r"(r[3]) : "r"(addr) : "memory");
}
__device__ __forceinline__ void mma16816(float* c, const uint32_t* a, const uint32_t* b) {
    asm volatile("mma.sync.aligned.m16n8k16.row.col.f32.bf16.bf16.f32 "
                 "{%0,%1,%2,%3}, {%4,%5,%6,%7}, {%8,%9}, {%0,%1,%2,%3};"
                 : "+f"(c[0]), "+f"(c[1]), "+f"(c[2]), "+f"(c[3])
                 : "r"(a[0]), "r"(a[1]), "r"(a[2]), "r"(a[3]), "r"(b[0]), "r"(b[1]));
}
__device__ __forceinline__ uint32_t sw_off(int row, int chunk) {
    int phys = (chunk & 8) | ((chunk ^ row) & 7);
    return (uint32_t)(row * 256 + phys * 16);
}

__global__ void __launch_bounds__(256, 1) k_gemm_mma(float* __restrict__ C, int n) {
    extern __shared__ char smem[];
    uint32_t sb = smem_u32(smem);
    int tid = threadIdx.x, wid = tid >> 5, lane = tid & 31;
    int row0 = blockIdx.x * 128;

    // ---- load the 4 tiles (A_hi, A_lo rows row0..row0+127; B_hi, B_lo full) ----
    {
        const __nv_bfloat16* srcs[4] = { g_ahi + (size_t)row0 * DH, g_alo + (size_t)row0 * DH,
                                         g_bhi, g_blo };
        const int bases[4] = { SM_AHI, SM_ALO, SM_BHI, SM_BLO };
#pragma unroll
        for (int t4 = 0; t4 < 4; t4++) {
            const uint4* src = (const uint4*)srcs[t4];
#pragma unroll
            for (int j = 0; j < 8; j++) {
                int f = tid + 256 * j;          // 0..2047
                int row = f >> 4;
                int chunk = f & 15;
                *(uint4*)(smem + bases[t4] + sw_off(row, chunk)) = src[row * 16 + chunk];
            }
        }
    }
    __syncthreads();

    int warp_m = wid & 3;        // 4 groups of 32 rows
    int warp_n = wid >> 2;       // 2 groups of 64 cols

    // ldmatrix lane geometry
    int lr = lane & 7;
    int rowA0 = warp_m * 32 + ((lane >> 3) & 1) * 8 + lr;       // + mt*16
    int aHi = lane >> 4;                                        // chunk parity for A
    int rowB0 = warp_n * 64 + ((lane >> 4) & 1) * 8 + lr;       // + nt2*16
    int bHi = (lane >> 3) & 1;                                  // chunk parity for B

    float c[2][8][4];
#pragma unroll
    for (int mt = 0; mt < 2; mt++)
#pragma unroll
        for (int nt = 0; nt < 8; nt++)
#pragma unroll
            for (int q = 0; q < 4; q++) c[mt][nt][q] = 0.f;

#pragma unroll
    for (int p = 0; p < 3; p++) {
        uint32_t aBase = sb + (p == 2 ? SM_ALO : SM_AHI);
        uint32_t bBase = sb + (p == 1 ? SM_BLO : SM_BHI);
#pragma unroll
        for (int ks = 0; ks < 8; ks++) {
            uint32_t a[2][4];
#pragma unroll
            for (int mt = 0; mt < 2; mt++) {
                int row = rowA0 + mt * 16;
                int chunk = ks * 2 + aHi;
                ldm_x4(a[mt], aBase + sw_off(row, chunk));
            }
            uint32_t b[8][2];
#pragma unroll
            for (int nt2 = 0; nt2 < 4; nt2++) {
                uint32_t r[4];
                int row = rowB0 + nt2 * 16;
                int chunk = ks * 2 + bHi;
                ldm_x4(r, bBase + sw_off(row, chunk));
                b[2 * nt2][0] = r[0]; b[2 * nt2][1] = r[1];
                b[2 * nt2 + 1][0] = r[2]; b[2 * nt2 + 1][1] = r[3];
            }
#pragma unroll
            for (int mt = 0; mt < 2; mt++)
#pragma unroll
                for (int nt = 0; nt < 8; nt++)
                    mma16816(c[mt][nt], a[mt], b[nt]);
        }
    }

    // ---- epilogue: dinv scale + store ----
#pragma unroll
    for (int mt = 0; mt < 2; mt++) {
        int row = row0 + warp_m * 32 + mt * 16 + (lane >> 2);
        int col = warp_n * 64 + (lane & 3) * 2;
        float s0 = (row < n) ? g_dinv[row] : 0.f;
        float s1 = (row + 8 < n) ? g_dinv[row + 8] : 0.f;
#pragma unroll
        for (int nt = 0; nt < 8; nt++) {
            int cc = col + nt * 8;
            if (row < n)
                *(float2*)&C[(size_t)row * DH + cc] =
                    make_float2(c[mt][nt][0] * s0, c[mt][nt][1] * s0);
            if (row + 8 < n)
                *(float2*)&C[(size_t)(row + 8) * DH + cc] =
                    make_float2(c[mt][nt][2] * s1, c[mt][nt][3] * s1);
        }
    }
}

// -------- aggregation: one warp per node, float4 per lane, 4-way unrolled --------
__device__ __forceinline__ float4 agg_node(const float4* __restrict__ xw4, int c, int lane) {
    float4 acc = xw4[c * 32 + lane];   // self-loop (already dinv[c]-scaled)
    int s = g_off[c], e = g_off[c + 1];
    int k = s;
    for (; k + 4 <= e; k += 4) {
        int r0 = g_csr[k], r1 = g_csr[k + 1], r2 = g_csr[k + 2], r3 = g_csr[k + 3];
        float4 v0 = xw4[r0 * 32 + lane];
        float4 v1 = xw4[r1 * 32 + lane];
        float4 v2 = xw4[r2 * 32 + lane];
        float4 v3 = xw4[r3 * 32 + lane];
        acc.x += (v0.x + v1.x) + (v2.x + v3.x);
        acc.y += (v0.y + v1.y) + (v2.y + v3.y);
        acc.z += (v0.z + v1.z) + (v2.z + v3.z);
        acc.w += (v0.w + v1.w) + (v2.w + v3.w);
    }
    for (; k < e; k++) {
        float4 v = xw4[g_csr[k] * 32 + lane];
        acc.x += v.x; acc.y += v.y; acc.z += v.z; acc.w += v.w;
    }
    return acc;
}

__global__ void k_agg(const float4* __restrict__ xw4, const float4* __restrict__ bias4,
                      float4* __restrict__ out4, int n) {
    int warp = threadIdx.x >> 5, lane = threadIdx.x & 31;
    int c = blockIdx.x * 4 + warp;
    if (c >= n) return;
    float4 acc = agg_node(xw4, c, lane);
    float di = g_dinv[c];
    float4 b = bias4[lane];
    float4 o;
    o.x = fmaxf(fmaf(di, acc.x, b.x), 0.f);
    o.y = fmaxf(fmaf(di, acc.y, b.y), 0.f);
    o.z = fmaxf(fmaf(di, acc.z, b.z), 0.f);
    o.w = fmaxf(fmaf(di, acc.w, b.w), 0.f);
    out4[c * 32 + lane] = o;
}

// layer-1 variant: writes bf16 hi/lo split directly (input of next GEMM)
__global__ void k_agg_split(const float4* __restrict__ xw4, const float4* __restrict__ bias4, int n) {
    int warp = threadIdx.x >> 5, lane = threadIdx.x & 31;
    int c = blockIdx.x * 4 + warp;
    if (c >= n) return;
    float4 acc = agg_node(xw4, c, lane);
    float di = g_dinv[c];
    float4 b = bias4[lane];
    float4 o;
    o.x = fmaxf(fmaf(di, acc.x, b.x), 0.f);
    o.y = fmaxf(fmaf(di, acc.y, b.y), 0.f);
    o.z = fmaxf(fmaf(di, acc.z, b.z), 0.f);
    o.w = fmaxf(fmaf(di, acc.w, b.w), 0.f);
    __nv_bfloat162 h01 = __floats2bfloat162_rn(o.x, o.y);
    __nv_bfloat162 h23 = __floats2bfloat162_rn(o.z, o.w);
    float2 f01 = __bfloat1622float2(h01);
    float2 f23 = __bfloat1622float2(h23);
    __nv_bfloat162 l01 = __floats2bfloat162_rn(o.x - f01.x, o.y - f01.y);
    __nv_bfloat162 l23 = __floats2bfloat162_rn(o.z - f23.x, o.w - f23.y);
    __nv_bfloat162* ah = (__nv_bfloat162*)g_ahi;
    __nv_bfloat162* al = (__nv_bfloat162*)g_alo;
    int bi = c * 64 + lane * 2;
    ah[bi] = h01; ah[bi + 1] = h23;
    al[bi] = l01; al[bi + 1] = l23;
}

// -------- per-node projection --------
__global__ void k_proj(const float* __restrict__ h, const float* __restrict__ Wfc, int n) {
    __shared__ float W[256 * 4];
    int t = threadIdx.x;
    for (int i = t; i < 1024; i += 256) W[i] = Wfc[i];
    __syncthreads();
    int warp = t >> 5, lane = t & 31;
    int node = blockIdx.x * 8 + warp;
    if (node >= n) return;
    float hv[4];
#pragma unroll
    for (int q = 0; q < 4; q++) hv[q] = h[node * 128 + lane + 32 * q];
    float p[8];
#pragma unroll
    for (int j = 0; j < 4; j++) {
        float a = 0.f, b = 0.f;
#pragma unroll
        for (int q = 0; q < 4; q++) {
            int k = lane + 32 * q;
            a = fmaf(hv[q], W[k * 4 + j], a);
            b = fmaf(hv[q], W[(128 + k) * 4 + j], b);
        }
        p[j] = a;
        p[4 + j] = b;
    }
#pragma unroll
    for (int j = 0; j < 8; j++) {
        float v = p[j];
#pragma unroll
        for (int o = 16; o > 0; o >>= 1) v += __shfl_xor_sync(0xffffffffu, v, o);
        if (lane == 0) g_p[node * 8 + j] = v;
    }
}

// -------- edge scoring + log-softmax --------
__global__ void k_edge(const int* __restrict__ ei, const float* __restrict__ bfc,
                       float* __restrict__ out, int E) {
    int e = blockIdx.x * blockDim.x + threadIdx.x;
    if (e >= E) return;
    int r = ei[e];
    int c = ei[E + e];
    float4 pa = *(const float4*)&g_p[r * 8];
    float4 pb = *(const float4*)&g_p[c * 8 + 4];
    float s0 = pa.x + pb.x + bfc[0];
    float s1 = pa.y + pb.y + bfc[1];
    float s2 = pa.z + pb.z + bfc[2];
    float s3 = pa.w + pb.w + bfc[3];
    float m = fmaxf(fmaxf(s0, s1), fmaxf(s2, s3));
    float t0 = expf(s0 - m), t1 = expf(s1 - m), t2 = expf(s2 - m), t3 = expf(s3 - m);
    float l = m + logf(t0 + t1 + t2 + t3);
    *(float4*)&out[e * 4] = make_float4(s0 - l, s1 - l, s2 - l, s3 - l);
}

extern "C" void kernel_launch(void* const* d_in, const int* in_sizes, int n_in,
                              void* d_out, int out_size) {
    const float* x   = (const float*)d_in[0];
    const int*   ei  = (const int*)d_in[1];
    const float* W1  = (const float*)d_in[2];
    const float* b1  = (const float*)d_in[3];
    const float* W2  = (const float*)d_in[4];
    const float* b2  = (const float*)d_in[5];
    const float* Wfc = (const float*)d_in[6];
    const float* bfc = (const float*)d_in[7];
    float* out = (float*)d_out;

    int n = in_sizes[0] / DH;
    int E = in_sizes[1] / 2;

    float *xw, *h;
    cudaGetSymbolAddress((void**)&xw, g_xw);
    cudaGetSymbolAddress((void**)&h, g_h);

    static int smem_set = 0;
    if (!smem_set) {
        cudaFuncSetAttribute(k_gemm_mma, cudaFuncAttributeMaxDynamicSharedMemorySize, SM_TOTAL);
        smem_set = 1;
    }

    int tb = 256;
    // CSR build
    k_zero<<<(n + tb - 1) / tb, tb>>>(n);
    k_hist<<<(E + tb - 1) / tb, tb>>>(ei, E);
    k_scan<<<1, 1024>>>(n);
    k_scatter<<<(E + tb - 1) / tb, tb>>>(ei, E);

    // input conversions
    k_convX<<<(NN_PAD * 32 + tb - 1) / tb, tb>>>((const float4*)x, n);
    k_convW<<<64, 256>>>(W1);

    // layer 1: HMMA GEMM + aggregation (writes bf16 split for layer 2)
    k_gemm_mma<<<NN_PAD / 128, 256, SM_TOTAL>>>(xw, n);
    k_agg_split<<<(n + 3) / 4, 128>>>((const float4*)xw, (const float4*)b1, n);

    // layer 2
    k_convW<<<64, 256>>>(W2);
    k_gemm_mma<<<NN_PAD / 128, 256, SM_TOTAL>>>(xw, n);
    k_agg<<<(n + 3) / 4, 128>>>((const float4*)xw, (const float4*)b2, (float4*)h, n);

    // edge classifier
    k_proj<<<(n + 7) / 8, 256>>>(h, Wfc, n);
    k_edge<<<(E + tb - 1) / tb, tb>>>(ei, bfc, out, E);
}

// round 6
// speedup vs baseline: 2.0814x; 1.6154x over previous
#include <cuda_runtime.h>
#include <cuda_bf16.h>
#include <cstdint>

#define NN 50000
#define NN_PAD 50048          // 391 * 128
#define EE 600000
#define DH 128
#define SCAN_G 49             // 49 * 1024 = 50176 >= NN

// -------- device scratch (no allocations allowed) --------
__device__ float g_xw[NN * DH];                 // dinv-scaled A@W
__device__ float g_h[NN * DH];                  // layer-2 output (fp32, for proj)
__device__ float g_dinv[NN];
__device__ int   g_count[NN];
__device__ int   g_off[NN + 1];
__device__ int   g_cursor[NN];
__device__ int   g_csr[EE];
__device__ int   g_bsum[SCAN_G];
__device__ int   g_bbase[SCAN_G];
__device__ float g_p[NN * 8];
__device__ __nv_bfloat16 g_ahi[NN_PAD * DH];    // bf16 split of current GEMM input
__device__ __nv_bfloat16 g_alo[NN_PAD * DH];
__device__ __nv_bfloat16 g_b1hi[DH * DH];       // bf16 split of W1^T / W2^T
__device__ __nv_bfloat16 g_b1lo[DH * DH];
__device__ __nv_bfloat16 g_b2hi[DH * DH];
__device__ __nv_bfloat16 g_b2lo[DH * DH];

__device__ __forceinline__ uint32_t smem_u32(const void* p) {
    uint32_t a;
    asm("{ .reg .u64 t; cvta.to.shared.u64 t, %1; cvt.u32.u64 %0, t; }" : "=r"(a) : "l"(p));
    return a;
}

// -------- CSR construction --------
__global__ void k_hist(const int* __restrict__ ei, int E) {
    int e = blockIdx.x * blockDim.x + threadIdx.x;
    if (e < E) atomicAdd(&g_count[ei[E + e]], 1);
}

__global__ void k_bsum(int n) {
    __shared__ int sh[1024];
    int tid = threadIdx.x;
    int i = blockIdx.x * 1024 + tid;
    int v = (i < n) ? g_count[i] : 0;
    sh[tid] = v;
    __syncthreads();
#pragma unroll
    for (int o = 512; o > 0; o >>= 1) {
        if (tid < o) sh[tid] += sh[tid + o];
        __syncthreads();
    }
    if (tid == 0) g_bsum[blockIdx.x] = sh[0];
}

__global__ void k_bscan() {
    if (threadIdx.x == 0) {
        int run = 0;
        for (int b = 0; b < SCAN_G; b++) { g_bbase[b] = run; run += g_bsum[b]; }
    }
}

__global__ void k_scan2(int n) {
    __shared__ int sh[1024];
    int tid = threadIdx.x;
    int i = blockIdx.x * 1024 + tid;
    int v = (i < n) ? g_count[i] : 0;
    sh[tid] = v;
    __syncthreads();
#pragma unroll
    for (int o = 1; o < 1024; o <<= 1) {
        int t = (tid >= o) ? sh[tid - o] : 0;
        __syncthreads();
        sh[tid] += t;
        __syncthreads();
    }
    if (i < n) {
        int excl = g_bbase[blockIdx.x] + sh[tid] - v;
        g_off[i] = excl;
        g_cursor[i] = excl;
        g_dinv[i] = rsqrtf((float)(v + 1));
        if (i == n - 1) g_off[n] = excl + v;
    }
}

__global__ void k_scatter(const int* __restrict__ ei, int E) {
    int e = blockIdx.x * blockDim.x + threadIdx.x;
    if (e < E) {
        int c = ei[E + e];
        int p = atomicAdd(&g_cursor[c], 1);
        g_csr[p] = ei[e];
    }
}

// -------- bf16 split conversions (also zeroes g_count for the histogram) --------
__global__ void k_convX(const float4* __restrict__ x4, int n) {
    int i = blockIdx.x * blockDim.x + threadIdx.x;   // float4 index
    if (i < NN) g_count[i] = 0;
    if (i >= NN_PAD * 32) return;
    int row = i >> 5;
    float4 v = (row < n) ? x4[i] : make_float4(0.f, 0.f, 0.f, 0.f);
    __nv_bfloat162 h01 = __floats2bfloat162_rn(v.x, v.y);
    __nv_bfloat162 h23 = __floats2bfloat162_rn(v.z, v.w);
    float2 f01 = __bfloat1622float2(h01);
    float2 f23 = __bfloat1622float2(h23);
    __nv_bfloat162 l01 = __floats2bfloat162_rn(v.x - f01.x, v.y - f01.y);
    __nv_bfloat162 l23 = __floats2bfloat162_rn(v.z - f23.x, v.w - f23.y);
    __nv_bfloat162* ah = (__nv_bfloat162*)g_ahi;
    __nv_bfloat162* al = (__nv_bfloat162*)g_alo;
    ah[i * 2] = h01; ah[i * 2 + 1] = h23;
    al[i * 2] = l01; al[i * 2 + 1] = l23;
}

// converts both W1 and W2 (transposed) in one launch; i in [0, 2*16384)
__global__ void k_convW2(const float* __restrict__ W1, const float* __restrict__ W2) {
    int i = blockIdx.x * blockDim.x + threadIdx.x;
    int which = i >> 14;
    int j = i & 16383;
    int nIdx = j >> 7, k = j & 127;
    const float* W = which ? W2 : W1;
    float v = W[k * DH + nIdx];                       // transpose: B[n][k] = W[k][n]
    __nv_bfloat16 h = __float2bfloat16(v);
    __nv_bfloat16 l = __float2bfloat16(v - __bfloat162float(h));
    if (which) { g_b2hi[j] = h; g_b2lo[j] = l; }
    else       { g_b1hi[j] = h; g_b1lo[j] = l; }
}

// ======================= mma.sync (HMMA) GEMM =======================
// C[row,:] = dinv[row] * (A[row,:] @ W) via 3-pass bf16 split.
#define SM_AHI  0
#define SM_ALO  32768
#define SM_BHI  65536
#define SM_BLO  98304
#define SM_TOTAL 131072

__device__ __forceinline__ void ldm_x4(uint32_t* r, uint32_t addr) {
    asm volatile("ldmatrix.sync.aligned.m8n8.x4.shared.b16 {%0,%1,%2,%3}, [%4];"
                 : "=r"(r[0]), "=r"(r[1]), "=r"(r[2]), "=r"(r[3]) : "r"(addr) : "memory");
}
__device__ __forceinline__ void mma16816(float* c, const uint32_t* a, const uint32_t* b) {
    asm volatile("mma.sync.aligned.m16n8k16.row.col.f32.bf16.bf16.f32 "
                 "{%0,%1,%2,%3}, {%4,%5,%6,%7}, {%8,%9}, {%0,%1,%2,%3};"
                 : "+f"(c[0]), "+f"(c[1]), "+f"(c[2]), "+f"(c[3])
                 : "r"(a[0]), "r"(a[1]), "r"(a[2]), "r"(a[3]), "r"(b[0]), "r"(b[1]));
}
__device__ __forceinline__ uint32_t sw_off(int row, int chunk) {
    int phys = (chunk & 8) | ((chunk ^ row) & 7);
    return (uint32_t)(row * 256 + phys * 16);
}

__global__ void __launch_bounds__(256, 1) k_gemm_mma(
        float* __restrict__ C,
        const __nv_bfloat16* __restrict__ bhi,
        const __nv_bfloat16* __restrict__ blo, int n) {
    extern __shared__ char smem[];
    uint32_t sb = smem_u32(smem);
    int tid = threadIdx.x, wid = tid >> 5, lane = tid & 31;
    int row0 = blockIdx.x * 128;

    {
        const __nv_bfloat16* srcs[4] = { g_ahi + (size_t)row0 * DH, g_alo + (size_t)row0 * DH,
                                         bhi, blo };
        const int bases[4] = { SM_AHI, SM_ALO, SM_BHI, SM_BLO };
#pragma unroll
        for (int t4 = 0; t4 < 4; t4++) {
            const uint4* src = (const uint4*)srcs[t4];
#pragma unroll
            for (int j = 0; j < 8; j++) {
                int f = tid + 256 * j;          // 0..2047
                int row = f >> 4;
                int chunk = f & 15;
                *(uint4*)(smem + bases[t4] + sw_off(row, chunk)) = src[row * 16 + chunk];
            }
        }
    }
    __syncthreads();

    int warp_m = wid & 3;
    int warp_n = wid >> 2;
    int lr = lane & 7;
    int rowA0 = warp_m * 32 + ((lane >> 3) & 1) * 8 + lr;
    int aHi = lane >> 4;
    int rowB0 = warp_n * 64 + ((lane >> 4) & 1) * 8 + lr;
    int bHi = (lane >> 3) & 1;

    float c[2][8][4];
#pragma unroll
    for (int mt = 0; mt < 2; mt++)
#pragma unroll
        for (int nt = 0; nt < 8; nt++)
#pragma unroll
            for (int q = 0; q < 4; q++) c[mt][nt][q] = 0.f;

#pragma unroll
    for (int p = 0; p < 3; p++) {
        uint32_t aBase = sb + (p == 2 ? SM_ALO : SM_AHI);
        uint32_t bBase = sb + (p == 1 ? SM_BLO : SM_BHI);
#pragma unroll
        for (int ks = 0; ks < 8; ks++) {
            uint32_t a[2][4];
#pragma unroll
            for (int mt = 0; mt < 2; mt++)
                ldm_x4(a[mt], aBase + sw_off(rowA0 + mt * 16, ks * 2 + aHi));
            uint32_t b[8][2];
#pragma unroll
            for (int nt2 = 0; nt2 < 4; nt2++) {
                uint32_t r[4];
                ldm_x4(r, bBase + sw_off(rowB0 + nt2 * 16, ks * 2 + bHi));
                b[2 * nt2][0] = r[0]; b[2 * nt2][1] = r[1];
                b[2 * nt2 + 1][0] = r[2]; b[2 * nt2 + 1][1] = r[3];
            }
#pragma unroll
            for (int mt = 0; mt < 2; mt++)
#pragma unroll
                for (int nt = 0; nt < 8; nt++)
                    mma16816(c[mt][nt], a[mt], b[nt]);
        }
    }

#pragma unroll
    for (int mt = 0; mt < 2; mt++) {
        int row = row0 + warp_m * 32 + mt * 16 + (lane >> 2);
        int col = warp_n * 64 + (lane & 3) * 2;
        float s0 = (row < n) ? g_dinv[row] : 0.f;
        float s1 = (row + 8 < n) ? g_dinv[row + 8] : 0.f;
#pragma unroll
        for (int nt = 0; nt < 8; nt++) {
            int cc = col + nt * 8;
            if (row < n)
                *(float2*)&C[(size_t)row * DH + cc] =
                    make_float2(c[mt][nt][0] * s0, c[mt][nt][1] * s0);
            if (row + 8 < n)
                *(float2*)&C[(size_t)(row + 8) * DH + cc] =
                    make_float2(c[mt][nt][2] * s1, c[mt][nt][3] * s1);
        }
    }
}

// -------- aggregation: one warp per node, float4 per lane, 8-way unrolled --------
__device__ __forceinline__ float4 agg_node(const float4* __restrict__ xw4, int c, int lane) {
    float4 acc = xw4[c * 32 + lane];   // self-loop (already dinv[c]-scaled)
    int s = g_off[c], e = g_off[c + 1];
    int k = s;
    for (; k + 8 <= e; k += 8) {
        int r[8];
#pragma unroll
        for (int j = 0; j < 8; j++) r[j] = g_csr[k + j];
        float4 v[8];
#pragma unroll
        for (int j = 0; j < 8; j++) v[j] = xw4[r[j] * 32 + lane];
        float4 s0, s1;
        s0.x = (v[0].x + v[1].x) + (v[2].x + v[3].x);
        s0.y = (v[0].y + v[1].y) + (v[2].y + v[3].y);
        s0.z = (v[0].z + v[1].z) + (v[2].z + v[3].z);
        s0.w = (v[0].w + v[1].w) + (v[2].w + v[3].w);
        s1.x = (v[4].x + v[5].x) + (v[6].x + v[7].x);
        s1.y = (v[4].y + v[5].y) + (v[6].y + v[7].y);
        s1.z = (v[4].z + v[5].z) + (v[6].z + v[7].z);
        s1.w = (v[4].w + v[5].w) + (v[6].w + v[7].w);
        acc.x += s0.x + s1.x;
        acc.y += s0.y + s1.y;
        acc.z += s0.z + s1.z;
        acc.w += s0.w + s1.w;
    }
    for (; k < e; k++) {
        float4 v = xw4[g_csr[k] * 32 + lane];
        acc.x += v.x; acc.y += v.y; acc.z += v.z; acc.w += v.w;
    }
    return acc;
}

__global__ void k_agg(const float4* __restrict__ xw4, const float4* __restrict__ bias4,
                      float4* __restrict__ out4, int n) {
    int warp = threadIdx.x >> 5, lane = threadIdx.x & 31;
    int c = blockIdx.x * 8 + warp;
    if (c >= n) return;
    float4 acc = agg_node(xw4, c, lane);
    float di = g_dinv[c];
    float4 b = bias4[lane];
    float4 o;
    o.x = fmaxf(fmaf(di, acc.x, b.x), 0.f);
    o.y = fmaxf(fmaf(di, acc.y, b.y), 0.f);
    o.z = fmaxf(fmaf(di, acc.z, b.z), 0.f);
    o.w = fmaxf(fmaf(di, acc.w, b.w), 0.f);
    out4[c * 32 + lane] = o;
}

// layer-1 variant: writes bf16 hi/lo split directly (input of next GEMM)
__global__ void k_agg_split(const float4* __restrict__ xw4, const float4* __restrict__ bias4, int n) {
    int warp = threadIdx.x >> 5, lane = threadIdx.x & 31;
    int c = blockIdx.x * 8 + warp;
    if (c >= n) return;
    float4 acc = agg_node(xw4, c, lane);
    float di = g_dinv[c];
    float4 b = bias4[lane];
    float4 o;
    o.x = fmaxf(fmaf(di, acc.x, b.x), 0.f);
    o.y = fmaxf(fmaf(di, acc.y, b.y), 0.f);
    o.z = fmaxf(fmaf(di, acc.z, b.z), 0.f);
    o.w = fmaxf(fmaf(di, acc.w, b.w), 0.f);
    __nv_bfloat162 h01 = __floats2bfloat162_rn(o.x, o.y);
    __nv_bfloat162 h23 = __floats2bfloat162_rn(o.z, o.w);
    float2 f01 = __bfloat1622float2(h01);
    float2 f23 = __bfloat1622float2(h23);
    __nv_bfloat162 l01 = __floats2bfloat162_rn(o.x - f01.x, o.y - f01.y);
    __nv_bfloat162 l23 = __floats2bfloat162_rn(o.z - f23.x, o.w - f23.y);
    __nv_bfloat162* ah = (__nv_bfloat162*)g_ahi;
    __nv_bfloat162* al = (__nv_bfloat162*)g_alo;
    int bi = c * 64 + lane * 2;
    ah[bi] = h01; ah[bi + 1] = h23;
    al[bi] = l01; al[bi + 1] = l23;
}

// -------- per-node projection --------
__global__ void k_proj(const float* __restrict__ h, const float* __restrict__ Wfc, int n) {
    __shared__ float W[256 * 4];
    int t = threadIdx.x;
    for (int i = t; i < 1024; i += 256) W[i] = Wfc[i];
    __syncthreads();
    int warp = t >> 5, lane = t & 31;
    int node = blockIdx.x * 8 + warp;
    if (node >= n) return;
    float hv[4];
#pragma unroll
    for (int q = 0; q < 4; q++) hv[q] = h[node * 128 + lane + 32 * q];
    float p[8];
#pragma unroll
    for (int j = 0; j < 4; j++) {
        float a = 0.f, b = 0.f;
#pragma unroll
        for (int q = 0; q < 4; q++) {
            int k = lane + 32 * q;
            a = fmaf(hv[q], W[k * 4 + j], a);
            b = fmaf(hv[q], W[(128 + k) * 4 + j], b);
        }
        p[j] = a;
        p[4 + j] = b;
    }
#pragma unroll
    for (int j = 0; j < 8; j++) {
        float v = p[j];
#pragma unroll
        for (int o = 16; o > 0; o >>= 1) v += __shfl_xor_sync(0xffffffffu, v, o);
        if (lane == 0) g_p[node * 8 + j] = v;
    }
}

// -------- edge scoring + log-softmax --------
__global__ void k_edge(const int* __restrict__ ei, const float* __restrict__ bfc,
                       float* __restrict__ out, int E) {
    int e = blockIdx.x * blockDim.x + threadIdx.x;
    if (e >= E) return;
    int r = ei[e];
    int c = ei[E + e];
    float4 pa = *(const float4*)&g_p[r * 8];
    float4 pb = *(const float4*)&g_p[c * 8 + 4];
    float s0 = pa.x + pb.x + bfc[0];
    float s1 = pa.y + pb.y + bfc[1];
    float s2 = pa.z + pb.z + bfc[2];
    float s3 = pa.w + pb.w + bfc[3];
    float m = fmaxf(fmaxf(s0, s1), fmaxf(s2, s3));
    float t0 = expf(s0 - m), t1 = expf(s1 - m), t2 = expf(s2 - m), t3 = expf(s3 - m);
    float l = m + logf(t0 + t1 + t2 + t3);
    *(float4*)&out[e * 4] = make_float4(s0 - l, s1 - l, s2 - l, s3 - l);
}

extern "C" void kernel_launch(void* const* d_in, const int* in_sizes, int n_in,
                              void* d_out, int out_size) {
    const float* x   = (const float*)d_in[0];
    const int*   ei  = (const int*)d_in[1];
    const float* W1  = (const float*)d_in[2];
    const float* b1  = (const float*)d_in[3];
    const float* W2  = (const float*)d_in[4];
    const float* b2  = (const float*)d_in[5];
    const float* Wfc = (const float*)d_in[6];
    const float* bfc = (const float*)d_in[7];
    float* out = (float*)d_out;

    int n = in_sizes[0] / DH;
    int E = in_sizes[1] / 2;

    float *xw, *h;
    cudaGetSymbolAddress((void**)&xw, g_xw);
    cudaGetSymbolAddress((void**)&h, g_h);
    __nv_bfloat16 *b1hi, *b1lo, *b2hi, *b2lo;
    cudaGetSymbolAddress((void**)&b1hi, g_b1hi);
    cudaGetSymbolAddress((void**)&b1lo, g_b1lo);
    cudaGetSymbolAddress((void**)&b2hi, g_b2hi);
    cudaGetSymbolAddress((void**)&b2lo, g_b2lo);

    static int smem_set = 0;
    if (!smem_set) {
        cudaFuncSetAttribute(k_gemm_mma, cudaFuncAttributeMaxDynamicSharedMemorySize, SM_TOTAL);
        smem_set = 1;
    }

    int tb = 256;
    // conversions + count zeroing (fused)
    k_convX<<<(NN_PAD * 32 + tb - 1) / tb, tb>>>((const float4*)x, n);
    k_convW2<<<128, 256>>>(W1, W2);

    // CSR build (coalesced 3-phase scan)
    k_hist<<<(E + tb - 1) / tb, tb>>>(ei, E);
    k_bsum<<<SCAN_G, 1024>>>(n);
    k_bscan<<<1, 32>>>();
    k_scan2<<<SCAN_G, 1024>>>(n);
    k_scatter<<<(E + tb - 1) / tb, tb>>>(ei, E);

    // layer 1
    k_gemm_mma<<<NN_PAD / 128, 256, SM_TOTAL>>>(xw, b1hi, b1lo, n);
    k_agg_split<<<(n + 7) / 8, 256>>>((const float4*)xw, (const float4*)b1, n);

    // layer 2
    k_gemm_mma<<<NN_PAD / 128, 256, SM_TOTAL>>>(xw, b2hi, b2lo, n);
    k_agg<<<(n + 7) / 8, 256>>>((const float4*)xw, (const float4*)b2, (float4*)h, n);

    // edge classifier
    k_proj<<<(n + 7) / 8, 256>>>(h, Wfc, n);
    k_edge<<<(E + tb - 1) / tb, tb>>>(ei, bfc, out, E);
}

// round 7
// speedup vs baseline: 2.2798x; 1.0953x over previous
#include <cuda_runtime.h>
#include <cuda_bf16.h>
#include <cuda_fp16.h>
#include <cstdint>

#define NN 50000
#define NN_PAD 50048          // 391 * 128
#define EE 600000
#define DH 128
#define SCAN_G 49             // 49 * 1024 = 50176 >= NN

// -------- device scratch (no allocations allowed) --------
__device__ __half g_xwh[NN * DH];               // dinv-scaled A@W, fp16
__device__ float g_h[NN * DH];                  // layer-2 output (fp32, for proj)
__device__ float g_dinv[NN];
__device__ int   g_count[NN];
__device__ int   g_off[NN + 1];
__device__ int   g_cursor[NN];
__device__ int   g_csr[EE];
__device__ int   g_bsum[SCAN_G];
__device__ int   g_bbase[SCAN_G];
__device__ int   g_tick;
__device__ float g_p[NN * 8];
__device__ __nv_bfloat16 g_ahi[NN_PAD * DH];    // bf16 split of current GEMM input
__device__ __nv_bfloat16 g_alo[NN_PAD * DH];
__device__ __nv_bfloat16 g_b1hi[DH * DH];       // bf16 split of W1^T / W2^T
__device__ __nv_bfloat16 g_b1lo[DH * DH];
__device__ __nv_bfloat16 g_b2hi[DH * DH];
__device__ __nv_bfloat16 g_b2lo[DH * DH];

__device__ __forceinline__ uint32_t smem_u32(const void* p) {
    uint32_t a;
    asm("{ .reg .u64 t; cvta.to.shared.u64 t, %1; cvt.u32.u64 %0, t; }" : "=r"(a) : "l"(p));
    return a;
}

// -------- fused prep: x -> bf16 split, W1/W2 -> transposed bf16 split, zero counts --------
__global__ void k_prep(const float4* __restrict__ x4,
                       const float* __restrict__ W1, const float* __restrict__ W2, int n) {
    int i = blockIdx.x * blockDim.x + threadIdx.x;
    if (i < NN) g_count[i] = 0;
    if (i < 2 * DH * DH) {
        int which = i >> 14;
        int j = i & 16383;
        int nIdx = j >> 7, k = j & 127;
        const float* W = which ? W2 : W1;
        float v = W[k * DH + nIdx];               // transpose: B[n][k] = W[k][n]
        __nv_bfloat16 h = __float2bfloat16(v);
        __nv_bfloat16 l = __float2bfloat16(v - __bfloat162float(h));
        if (which) { g_b2hi[j] = h; g_b2lo[j] = l; }
        else       { g_b1hi[j] = h; g_b1lo[j] = l; }
    }
    if (i >= NN_PAD * 32) return;
    int row = i >> 5;
    float4 v = (row < n) ? x4[i] : make_float4(0.f, 0.f, 0.f, 0.f);
    __nv_bfloat162 h01 = __floats2bfloat162_rn(v.x, v.y);
    __nv_bfloat162 h23 = __floats2bfloat162_rn(v.z, v.w);
    float2 f01 = __bfloat1622float2(h01);
    float2 f23 = __bfloat1622float2(h23);
    __nv_bfloat162 l01 = __floats2bfloat162_rn(v.x - f01.x, v.y - f01.y);
    __nv_bfloat162 l23 = __floats2bfloat162_rn(v.z - f23.x, v.w - f23.y);
    __nv_bfloat162* ah = (__nv_bfloat162*)g_ahi;
    __nv_bfloat162* al = (__nv_bfloat162*)g_alo;
    ah[i * 2] = h01; ah[i * 2 + 1] = h23;
    al[i * 2] = l01; al[i * 2 + 1] = l23;
}

// -------- CSR construction --------
__global__ void k_hist(const int* __restrict__ ei, int E) {
    int e = blockIdx.x * blockDim.x + threadIdx.x;
    if (e < E) atomicAdd(&g_count[ei[E + e]], 1);
}

// block sums + last-block scan of the 49 block sums (fused)
__global__ void k_bsum(int n) {
    __shared__ int sh[1024];
    int tid = threadIdx.x;
    int i = blockIdx.x * 1024 + tid;
    sh[tid] = (i < n) ? g_count[i] : 0;
    __syncthreads();
#pragma unroll
    for (int o = 512; o > 0; o >>= 1) {
        if (tid < o) sh[tid] += sh[tid + o];
        __syncthreads();
    }
    if (tid == 0) {
        g_bsum[blockIdx.x] = sh[0];
        __threadfence();
        int t = atomicAdd(&g_tick, 1);
        if (t == SCAN_G - 1) {
            g_tick = 0;                       // reset for next graph replay
            int run = 0;
            for (int b = 0; b < SCAN_G; b++) { g_bbase[b] = run; run += g_bsum[b]; }
        }
    }
}

__global__ void k_scan2(int n) {
    __shared__ int sh[1024];
    int tid = threadIdx.x;
    int i = blockIdx.x * 1024 + tid;
    int v = (i < n) ? g_count[i] : 0;
    sh[tid] = v;
    __syncthreads();
#pragma unroll
    for (int o = 1; o < 1024; o <<= 1) {
        int t = (tid >= o) ? sh[tid - o] : 0;
        __syncthreads();
        sh[tid] += t;
        __syncthreads();
    }
    if (i < n) {
        int excl = g_bbase[blockIdx.x] + sh[tid] - v;
        g_off[i] = excl;
        g_cursor[i] = excl;
        g_dinv[i] = rsqrtf((float)(v + 1));
        if (i == n - 1) g_off[n] = excl + v;
    }
}

__global__ void k_scatter(const int* __restrict__ ei, int E) {
    int e = blockIdx.x * blockDim.x + threadIdx.x;
    if (e < E) {
        int c = ei[E + e];
        int p = atomicAdd(&g_cursor[c], 1);
        g_csr[p] = ei[e];
    }
}

// ======================= mma.sync (HMMA) GEMM =======================
// xwh[row,:] = fp16( dinv[row] * (A[row,:] @ W) ) via 3-pass bf16 split.
#define SM_AHI  0
#define SM_ALO  32768
#define SM_BHI  65536
#define SM_BLO  98304
#define SM_TOTAL 131072

__device__ __forceinline__ void ldm_x4(uint32_t* r, uint32_t addr) {
    asm volatile("ldmatrix.sync.aligned.m8n8.x4.shared.b16 {%0,%1,%2,%3}, [%4];"
                 : "=r"(r[0]), "=r"(r[1]), "=r"(r[2]), "=r"(r[3]) : "r"(addr) : "memory");
}
__device__ __forceinline__ void mma16816(float* c, const uint32_t* a, const uint32_t* b) {
    asm volatile("mma.sync.aligned.m16n8k16.row.col.f32.bf16.bf16.f32 "
                 "{%0,%1,%2,%3}, {%4,%5,%6,%7}, {%8,%9}, {%0,%1,%2,%3};"
                 : "+f"(c[0]), "+f"(c[1]), "+f"(c[2]), "+f"(c[3])
                 : "r"(a[0]), "r"(a[1]), "r"(a[2]), "r"(a[3]), "r"(b[0]), "r"(b[1]));
}
__device__ __forceinline__ uint32_t sw_off(int row, int chunk) {
    int phys = (chunk & 8) | ((chunk ^ row) & 7);
    return (uint32_t)(row * 256 + phys * 16);
}

__global__ void __launch_bounds__(256, 1) k_gemm_mma(
        __half* __restrict__ C,
        const __nv_bfloat16* __restrict__ bhi,
        const __nv_bfloat16* __restrict__ blo, int n) {
    extern __shared__ char smem[];
    uint32_t sb = smem_u32(smem);
    int tid = threadIdx.x, wid = tid >> 5, lane = tid & 31;
    int row0 = blockIdx.x * 128;

    {
        const __nv_bfloat16* srcs[4] = { g_ahi + (size_t)row0 * DH, g_alo + (size_t)row0 * DH,
                                         bhi, blo };
        const int bases[4] = { SM_AHI, SM_ALO, SM_BHI, SM_BLO };
#pragma unroll
        for (int t4 = 0; t4 < 4; t4++) {
            const uint4* src = (const uint4*)srcs[t4];
#pragma unroll
            for (int j = 0; j < 8; j++) {
                int f = tid + 256 * j;          // 0..2047
                int row = f >> 4;
                int chunk = f & 15;
                *(uint4*)(smem + bases[t4] + sw_off(row, chunk)) = src[row * 16 + chunk];
            }
        }
    }
    __syncthreads();

    int warp_m = wid & 3;
    int warp_n = wid >> 2;
    int lr = lane & 7;
    int rowA0 = warp_m * 32 + ((lane >> 3) & 1) * 8 + lr;
    int aHi = lane >> 4;
    int rowB0 = warp_n * 64 + ((lane >> 4) & 1) * 8 + lr;
    int bHi = (lane >> 3) & 1;

    float c[2][8][4];
#pragma unroll
    for (int mt = 0; mt < 2; mt++)
#pragma unroll
        for (int nt = 0; nt < 8; nt++)
#pragma unroll
            for (int q = 0; q < 4; q++) c[mt][nt][q] = 0.f;

#pragma unroll
    for (int p = 0; p < 3; p++) {
        uint32_t aBase = sb + (p == 2 ? SM_ALO : SM_AHI);
        uint32_t bBase = sb + (p == 1 ? SM_BLO : SM_BHI);
#pragma unroll
        for (int ks = 0; ks < 8; ks++) {
            uint32_t a[2][4];
#pragma unroll
            for (int mt = 0; mt < 2; mt++)
                ldm_x4(a[mt], aBase + sw_off(rowA0 + mt * 16, ks * 2 + aHi));
            uint32_t b[8][2];
#pragma unroll
            for (int nt2 = 0; nt2 < 4; nt2++) {
                uint32_t r[4];
                ldm_x4(r, bBase + sw_off(rowB0 + nt2 * 16, ks * 2 + bHi));
                b[2 * nt2][0] = r[0]; b[2 * nt2][1] = r[1];
                b[2 * nt2 + 1][0] = r[2]; b[2 * nt2 + 1][1] = r[3];
            }
#pragma unroll
            for (int mt = 0; mt < 2; mt++)
#pragma unroll
                for (int nt = 0; nt < 8; nt++)
                    mma16816(c[mt][nt], a[mt], b[nt]);
        }
    }

#pragma unroll
    for (int mt = 0; mt < 2; mt++) {
        int row = row0 + warp_m * 32 + mt * 16 + (lane >> 2);
        int col = warp_n * 64 + (lane & 3) * 2;
        float s0 = (row < n) ? g_dinv[row] : 0.f;
        float s1 = (row + 8 < n) ? g_dinv[row + 8] : 0.f;
#pragma unroll
        for (int nt = 0; nt < 8; nt++) {
            int cc = col + nt * 8;
            if (row < n)
                *(__half2*)&C[(size_t)row * DH + cc] =
                    __floats2half2_rn(c[mt][nt][0] * s0, c[mt][nt][1] * s0);
            if (row + 8 < n)
                *(__half2*)&C[(size_t)(row + 8) * DH + cc] =
                    __floats2half2_rn(c[mt][nt][2] * s1, c[mt][nt][3] * s1);
        }
    }
}

// -------- aggregation: one warp per node, fp16 rows (uint2 = 4 halves/lane), fp32 accum --------
__device__ __forceinline__ float4 agg_node(const uint2* __restrict__ xwh, int c, int lane) {
    uint2 sv = xwh[c * 32 + lane];                 // self-loop term
    float2 a01 = __half22float2(*(__half2*)&sv.x);
    float2 a23 = __half22float2(*(__half2*)&sv.y);
    float4 acc = make_float4(a01.x, a01.y, a23.x, a23.y);
    int s = g_off[c], e = g_off[c + 1];
    int k = s;
    for (; k + 8 <= e; k += 8) {
        int r[8];
#pragma unroll
        for (int j = 0; j < 8; j++) r[j] = g_csr[k + j];
        uint2 v[8];
#pragma unroll
        for (int j = 0; j < 8; j++) v[j] = xwh[r[j] * 32 + lane];
#pragma unroll
        for (int j = 0; j < 8; j++) {
            float2 f01 = __half22float2(*(__half2*)&v[j].x);
            float2 f23 = __half22float2(*(__half2*)&v[j].y);
            acc.x += f01.x; acc.y += f01.y; acc.z += f23.x; acc.w += f23.y;
        }
    }
    for (; k < e; k++) {
        uint2 v = xwh[g_csr[k] * 32 + lane];
        float2 f01 = __half22float2(*(__half2*)&v.x);
        float2 f23 = __half22float2(*(__half2*)&v.y);
        acc.x += f01.x; acc.y += f01.y; acc.z += f23.x; acc.w += f23.y;
    }
    return acc;
}

__global__ void k_agg(const uint2* __restrict__ xwh, const float4* __restrict__ bias4,
                      float4* __restrict__ out4, int n) {
    int warp = threadIdx.x >> 5, lane = threadIdx.x & 31;
    int c = blockIdx.x * 8 + warp;
    if (c >= n) return;
    float4 acc = agg_node(xwh, c, lane);
    float di = g_dinv[c];
    float4 b = bias4[lane];
    float4 o;
    o.x = fmaxf(fmaf(di, acc.x, b.x), 0.f);
    o.y = fmaxf(fmaf(di, acc.y, b.y), 0.f);
    o.z = fmaxf(fmaf(di, acc.z, b.z), 0.f);
    o.w = fmaxf(fmaf(di, acc.w, b.w), 0.f);
    out4[c * 32 + lane] = o;
}

// layer-1 variant: writes bf16 hi/lo split directly (input of next GEMM)
__global__ void k_agg_split(const uint2* __restrict__ xwh, const float4* __restrict__ bias4, int n) {
    int warp = threadIdx.x >> 5, lane = threadIdx.x & 31;
    int c = blockIdx.x * 8 + warp;
    if (c >= n) return;
    float4 acc = agg_node(xwh, c, lane);
    float di = g_dinv[c];
    float4 b = bias4[lane];
    float4 o;
    o.x = fmaxf(fmaf(di, acc.x, b.x), 0.f);
    o.y = fmaxf(fmaf(di, acc.y, b.y), 0.f);
    o.z = fmaxf(fmaf(di, acc.z, b.z), 0.f);
    o.w = fmaxf(fmaf(di, acc.w, b.w), 0.f);
    __nv_bfloat162 h01 = __floats2bfloat162_rn(o.x, o.y);
    __nv_bfloat162 h23 = __floats2bfloat162_rn(o.z, o.w);
    float2 f01 = __bfloat1622float2(h01);
    float2 f23 = __bfloat1622float2(h23);
    __nv_bfloat162 l01 = __floats2bfloat162_rn(o.x - f01.x, o.y - f01.y);
    __nv_bfloat162 l23 = __floats2bfloat162_rn(o.z - f23.x, o.w - f23.y);
    __nv_bfloat162* ah = (__nv_bfloat162*)g_ahi;
    __nv_bfloat162* al = (__nv_bfloat162*)g_alo;
    int bi = c * 64 + lane * 2;
    ah[bi] = h01; ah[bi + 1] = h23;
    al[bi] = l01; al[bi + 1] = l23;
}

// -------- per-node projection --------
__global__ void k_proj(const float* __restrict__ h, const float* __restrict__ Wfc, int n) {
    __shared__ float W[256 * 4];
    int t = threadIdx.x;
    for (int i = t; i < 1024; i += 256) W[i] = Wfc[i];
    __syncthreads();
    int warp = t >> 5, lane = t & 31;
    int node = blockIdx.x * 8 + warp;
    if (node >= n) return;
    float hv[4];
#pragma unroll
    for (int q = 0; q < 4; q++) hv[q] = h[node * 128 + lane + 32 * q];
    float p[8];
#pragma unroll
    for (int j = 0; j < 4; j++) {
        float a = 0.f, b = 0.f;
#pragma unroll
        for (int q = 0; q < 4; q++) {
            int k = lane + 32 * q;
            a = fmaf(hv[q], W[k * 4 + j], a);
            b = fmaf(hv[q], W[(128 + k) * 4 + j], b);
        }
        p[j] = a;
        p[4 + j] = b;
    }
#pragma unroll
    for (int j = 0; j < 8; j++) {
        float v = p[j];
#pragma unroll
        for (int o = 16; o > 0; o >>= 1) v += __shfl_xor_sync(0xffffffffu, v, o);
        if (lane == 0) g_p[node * 8 + j] = v;
    }
}

// -------- edge scoring + log-softmax --------
__global__ void k_edge(const int* __restrict__ ei, const float* __restrict__ bfc,
                       float* __restrict__ out, int E) {
    int e = blockIdx.x * blockDim.x + threadIdx.x;
    if (e >= E) return;
    int r = ei[e];
    int c = ei[E + e];
    float4 pa = *(const float4*)&g_p[r * 8];
    float4 pb = *(const float4*)&g_p[c * 8 + 4];
    float s0 = pa.x + pb.x + bfc[0];
    float s1 = pa.y + pb.y + bfc[1];
    float s2 = pa.z + pb.z + bfc[2];
    float s3 = pa.w + pb.w + bfc[3];
    float m = fmaxf(fmaxf(s0, s1), fmaxf(s2, s3));
    float t0 = expf(s0 - m), t1 = expf(s1 - m), t2 = expf(s2 - m), t3 = expf(s3 - m);
    float l = m + logf(t0 + t1 + t2 + t3);
    *(float4*)&out[e * 4] = make_float4(s0 - l, s1 - l, s2 - l, s3 - l);
}

extern "C" void kernel_launch(void* const* d_in, const int* in_sizes, int n_in,
                              void* d_out, int out_size) {
    const float* x   = (const float*)d_in[0];
    const int*   ei  = (const int*)d_in[1];
    const float* W1  = (const float*)d_in[2];
    const float* b1  = (const float*)d_in[3];
    const float* W2  = (const float*)d_in[4];
    const float* b2  = (const float*)d_in[5];
    const float* Wfc = (const float*)d_in[6];
    const float* bfc = (const float*)d_in[7];
    float* out = (float*)d_out;

    int n = in_sizes[0] / DH;
    int E = in_sizes[1] / 2;

    __half* xwh;
    float* h;
    cudaGetSymbolAddress((void**)&xwh, g_xwh);
    cudaGetSymbolAddress((void**)&h, g_h);
    __nv_bfloat16 *b1hi, *b1lo, *b2hi, *b2lo;
    cudaGetSymbolAddress((void**)&b1hi, g_b1hi);
    cudaGetSymbolAddress((void**)&b1lo, g_b1lo);
    cudaGetSymbolAddress((void**)&b2hi, g_b2hi);
    cudaGetSymbolAddress((void**)&b2lo, g_b2lo);

    static int smem_set = 0;
    if (!smem_set) {
        cudaFuncSetAttribute(k_gemm_mma, cudaFuncAttributeMaxDynamicSharedMemorySize, SM_TOTAL);
        smem_set = 1;
    }

    int tb = 256;
    // fused conversions + count zeroing
    k_prep<<<(NN_PAD * 32 + tb - 1) / tb, tb>>>((const float4*)x, W1, W2, n);

    // CSR build
    k_hist<<<(E + tb - 1) / tb, tb>>>(ei, E);
    k_bsum<<<SCAN_G, 1024>>>(n);
    k_scan2<<<SCAN_G, 1024>>>(n);
    k_scatter<<<(E + tb - 1) / tb, tb>>>(ei, E);

    // layer 1
    k_gemm_mma<<<NN_PAD / 128, 256, SM_TOTAL>>>(xwh, b1hi, b1lo, n);
    k_agg_split<<<(n + 7) / 8, 256>>>((const uint2*)xwh, (const float4*)b1, n);

    // layer 2
    k_gemm_mma<<<NN_PAD / 128, 256, SM_TOTAL>>>(xwh, b2hi, b2lo, n);
    k_agg<<<(n + 7) / 8, 256>>>((const uint2*)xwh, (const float4*)b2, (float4*)h, n);

    // edge classifier
    k_proj<<<(n + 7) / 8, 256>>>(h, Wfc, n);
    k_edge<<<(E + tb - 1) / tb, tb>>>(ei, bfc, out, E);
}